// round 4
// baseline (speedup 1.0000x reference)
#include <cuda_runtime.h>
#include <stdint.h>

#define CIN    64
#define COUT   64
#define HW     16384     // 128*128
#define NGRP   16        // input-channel groups of 4
#define NCHUNK 1024      // 524288 positions / (256 threads * 2 pos)
#define GRID   444       // 148 SMs * 3 CTAs

__device__ __forceinline__ int dp4a_us(unsigned a, int b, int c) {
    int r;
    asm("dp4a.u32.s32 %0, %1, %2, %3;" : "=r"(r) : "r"(a), "r"(b), "r"(c));
    return r;
}

__device__ __forceinline__ unsigned pack4(int a, int b, int c, int d) {
    unsigned lo = __byte_perm((unsigned)a, (unsigned)b, 0x0040);
    unsigned hi = __byte_perm((unsigned)c, (unsigned)d, 0x0040);
    return __byte_perm(lo, hi, 0x5410);
}

__global__ __launch_bounds__(256, 3) void conv_fused(
    const int2*  __restrict__ x,
    float2*      __restrict__ out,
    const int*   __restrict__ w,
    const float* __restrict__ wscale,
    const int*   __restrict__ wzp,
    const float* __restrict__ bias,
    const float* __restrict__ iscale,
    const float* __restrict__ oscale,
    const int*   __restrict__ izp_p,
    const int*   __restrict__ ozp_p)
{
    __shared__ int    s_w[NGRP * COUT];   // [group][o] packed s8 weights
    __shared__ float4 s_P[COUT];          // (S, C0, C1, 0) per output channel

    int tid = threadIdx.x;

    // ---- inlined prep: threads 0..63 each build one output channel ----
    if (tid < COUT) {
        int o = tid;
        int sum = 0;
#pragma unroll
        for (int g = 0; g < NGRP; g++) {
            unsigned word = 0;
#pragma unroll
            for (int j = 0; j < 4; j++) {
                int v = __ldg(w + o * CIN + g * 4 + j);
                sum += v;
                word |= (unsigned)(v & 0xFF) << (8 * j);
            }
            s_w[g * COUT + o] = (int)word;
        }
        float s   = iscale[0] * wscale[o] / oscale[0];
        float izp = (float)izp_p[0];
        float zw  = (float)wzp[o];
        // round(f)+ozp == round(f+ozp) for integer ozp -> fold ozp into C0
        float C0  = bias[o] / oscale[0]
                  + s * izp * (64.0f * zw - (float)sum)
                  + (float)ozp_p[0];
        s_P[o] = make_float4(s, C0, -s * zw, 0.0f);
    }
    __syncthreads();

    // ---- persistent grid-stride loop over position-pair chunks ----
    for (int chunk = blockIdx.x; chunk < NCHUNK; chunk += GRID) {
        int gp = (chunk * 256 + tid) << 1;   // 2 consecutive w positions
        int b  = gp >> 14;                    // / HW
        int hw = gp & (HW - 1);

        const int2* xb = x + (b * (CIN * HW / 2) + (hw >> 1));

        // load 64 channels x 2 positions; pack to u8x4 words per (group, pos)
        unsigned xw[NGRP][2];
#pragma unroll
        for (int g = 0; g < NGRP; g++) {
            int2 a0 = __ldcs(xb + (g * 4 + 0) * (HW / 2));
            int2 a1 = __ldcs(xb + (g * 4 + 1) * (HW / 2));
            int2 a2 = __ldcs(xb + (g * 4 + 2) * (HW / 2));
            int2 a3 = __ldcs(xb + (g * 4 + 3) * (HW / 2));
            xw[g][0] = pack4(a0.x, a1.x, a2.x, a3.x);
            xw[g][1] = pack4(a0.y, a1.y, a2.y, a3.y);
        }

        // per-position channel sums (weight zero-point term)
        int sx0 = 0, sx1 = 0;
#pragma unroll
        for (int g = 0; g < NGRP; g++) {
            sx0 = dp4a_us(xw[g][0], 0x01010101, sx0);
            sx1 = dp4a_us(xw[g][1], 0x01010101, sx1);
        }
        float sxf0 = (float)sx0, sxf1 = (float)sx1;

        const int out_base = b * COUT * (HW / 2) + (hw >> 1);  // float2 units

        for (int q = 0; q < NGRP; q++) {     // 16 output-channel quads
            int acc[4][2] = {};
#pragma unroll
            for (int g = 0; g < NGRP; g++) {
                int4 w4 = *(const int4*)(s_w + g * COUT + q * 4);
                acc[0][0] = dp4a_us(xw[g][0], w4.x, acc[0][0]);
                acc[0][1] = dp4a_us(xw[g][1], w4.x, acc[0][1]);
                acc[1][0] = dp4a_us(xw[g][0], w4.y, acc[1][0]);
                acc[1][1] = dp4a_us(xw[g][1], w4.y, acc[1][1]);
                acc[2][0] = dp4a_us(xw[g][0], w4.z, acc[2][0]);
                acc[2][1] = dp4a_us(xw[g][1], w4.z, acc[2][1]);
                acc[3][0] = dp4a_us(xw[g][0], w4.w, acc[3][0]);
                acc[3][1] = dp4a_us(xw[g][1], w4.w, acc[3][1]);
            }
#pragma unroll
            for (int j = 0; j < 4; j++) {
                int o = q * 4 + j;
                float4 P = s_P[o];            // one LDS.128: S, C0, C1
                float f0 = fmaf(P.x, (float)acc[j][0], fmaf(P.z, sxf0, P.y));
                float f1 = fmaf(P.x, (float)acc[j][1], fmaf(P.z, sxf1, P.y));
                float r0 = fminf(fmaxf(rintf(f0), 0.0f), 255.0f);
                float r1 = fminf(fmaxf(rintf(f1), 0.0f), 255.0f);
                __stcs(&out[out_base + o * (HW / 2)], make_float2(r0, r1));
            }
        }
    }
}

extern "C" void kernel_launch(void* const* d_in, const int* in_sizes, int n_in,
                              void* d_out, int out_size) {
    // metadata order:
    // 0: x_quant (int32)       1: input_scale (f32)   2: input_zero_point (i32)
    // 3: weight_int8 (i32)     4: weight_scale (f32)  5: weight_zero_point (i32)
    // 6: bias_fp32 (f32)       7: output_scale (f32)  8: output_zero_point (i32)
    (void)in_sizes; (void)n_in; (void)out_size;

    conv_fused<<<GRID, 256>>>((const int2*)d_in[0], (float2*)d_out,
                              (const int*)d_in[3], (const float*)d_in[4],
                              (const int*)d_in[5], (const float*)d_in[6],
                              (const float*)d_in[1], (const float*)d_in[7],
                              (const int*)d_in[2], (const int*)d_in[8]);
}

// round 5
// speedup vs baseline: 1.1068x; 1.1068x over previous
#include <cuda_runtime.h>
#include <stdint.h>

#define CIN    64
#define COUT   64
#define HW     16384     // 128*128
#define NGRP   16        // input-channel groups of 4

__device__ __forceinline__ int dp4a_us(unsigned a, int b, int c) {
    int r;
    asm("dp4a.u32.s32 %0, %1, %2, %3;" : "=r"(r) : "r"(a), "r"(b), "r"(c));
    return r;
}

__device__ __forceinline__ unsigned pack4(int a, int b, int c, int d) {
    unsigned lo = __byte_perm((unsigned)a, (unsigned)b, 0x0040);
    unsigned hi = __byte_perm((unsigned)c, (unsigned)d, 0x0040);
    return __byte_perm(lo, hi, 0x5410);
}

__global__ __launch_bounds__(256, 3) void conv_fused(
    const int2*  __restrict__ x,
    float2*      __restrict__ out,
    const int4*  __restrict__ w,      // weight as int4 quads (contiguous)
    const float* __restrict__ wscale,
    const int*   __restrict__ wzp,
    const float* __restrict__ bias,
    const float* __restrict__ iscale,
    const float* __restrict__ oscale,
    const int*   __restrict__ izp_p,
    const int*   __restrict__ ozp_p)
{
    __shared__ int    s_w[NGRP * COUT];   // [group][o] packed s8 weights
    __shared__ float4 s_P[COUT];          // (S, C0, C1, 0) per output channel

    int tid = threadIdx.x;

    // ---- inlined prep: threads 0..63 each build one output channel ----
    if (tid < COUT) {
        int o = tid;
        int sum = 0;
#pragma unroll
        for (int g = 0; g < NGRP; g++) {
            int4 v = __ldg(w + o * NGRP + g);   // w[o*64 + g*4 .. +3]
            sum += v.x + v.y + v.z + v.w;
            s_w[g * COUT + o] = (int)pack4(v.x, v.y, v.z, v.w);
        }
        float s   = iscale[0] * wscale[o] / oscale[0];
        float izp = (float)izp_p[0];
        float zw  = (float)wzp[o];
        // round(f)+ozp == round(f+ozp) for integer ozp -> fold ozp into C0
        float C0  = bias[o] / oscale[0]
                  + s * izp * (64.0f * zw - (float)sum)
                  + (float)ozp_p[0];
        s_P[o] = make_float4(s, C0, -s * zw, 0.0f);
    }
    __syncthreads();

    // ---- one chunk per block (R3 structure: front-batched loads) ----
    int gp = (blockIdx.x * 256 + tid) << 1;  // 2 consecutive w positions
    int b  = gp >> 14;                        // / HW
    int hw = gp & (HW - 1);

    const int2* xb = x + (b * (CIN * HW / 2) + (hw >> 1));

    // load 64 channels x 2 positions; pack to u8x4 words per (group, pos)
    unsigned xw[NGRP][2];
#pragma unroll
    for (int g = 0; g < NGRP; g++) {
        int2 a0 = __ldg(xb + (g * 4 + 0) * (HW / 2));
        int2 a1 = __ldg(xb + (g * 4 + 1) * (HW / 2));
        int2 a2 = __ldg(xb + (g * 4 + 2) * (HW / 2));
        int2 a3 = __ldg(xb + (g * 4 + 3) * (HW / 2));
        xw[g][0] = pack4(a0.x, a1.x, a2.x, a3.x);
        xw[g][1] = pack4(a0.y, a1.y, a2.y, a3.y);
    }

    // per-position channel sums (weight zero-point term)
    int sx0 = 0, sx1 = 0;
#pragma unroll
    for (int g = 0; g < NGRP; g++) {
        sx0 = dp4a_us(xw[g][0], 0x01010101, sx0);
        sx1 = dp4a_us(xw[g][1], 0x01010101, sx1);
    }
    float sxf0 = (float)sx0, sxf1 = (float)sx1;

    const int out_base = b * COUT * (HW / 2) + (hw >> 1);  // float2 units

    for (int q = 0; q < NGRP; q++) {     // 16 output-channel quads
        int acc[4][2] = {};
#pragma unroll
        for (int g = 0; g < NGRP; g++) {
            int4 w4 = *(const int4*)(s_w + g * COUT + q * 4);
            acc[0][0] = dp4a_us(xw[g][0], w4.x, acc[0][0]);
            acc[0][1] = dp4a_us(xw[g][1], w4.x, acc[0][1]);
            acc[1][0] = dp4a_us(xw[g][0], w4.y, acc[1][0]);
            acc[1][1] = dp4a_us(xw[g][1], w4.y, acc[1][1]);
            acc[2][0] = dp4a_us(xw[g][0], w4.z, acc[2][0]);
            acc[2][1] = dp4a_us(xw[g][1], w4.z, acc[2][1]);
            acc[3][0] = dp4a_us(xw[g][0], w4.w, acc[3][0]);
            acc[3][1] = dp4a_us(xw[g][1], w4.w, acc[3][1]);
        }
#pragma unroll
        for (int j = 0; j < 4; j++) {
            int o = q * 4 + j;
            float4 P = s_P[o];            // one LDS.128: S, C0, C1
            float f0 = fmaf(P.x, (float)acc[j][0], fmaf(P.z, sxf0, P.y));
            float f1 = fmaf(P.x, (float)acc[j][1], fmaf(P.z, sxf1, P.y));
            float r0 = fminf(fmaxf(rintf(f0), 0.0f), 255.0f);
            float r1 = fminf(fmaxf(rintf(f1), 0.0f), 255.0f);
            out[out_base + o * (HW / 2)] = make_float2(r0, r1);
        }
    }
}

extern "C" void kernel_launch(void* const* d_in, const int* in_sizes, int n_in,
                              void* d_out, int out_size) {
    // metadata order:
    // 0: x_quant (int32)       1: input_scale (f32)   2: input_zero_point (i32)
    // 3: weight_int8 (i32)     4: weight_scale (f32)  5: weight_zero_point (i32)
    // 6: bias_fp32 (f32)       7: output_scale (f32)  8: output_zero_point (i32)
    (void)in_sizes; (void)n_in; (void)out_size;

    // 524288 positions / 2 per thread / 256 threads = 1024 blocks (exact)
    conv_fused<<<1024, 256>>>((const int2*)d_in[0], (float2*)d_out,
                              (const int4*)d_in[3], (const float*)d_in[4],
                              (const int*)d_in[5], (const float*)d_in[6],
                              (const float*)d_in[1], (const float*)d_in[7],
                              (const int*)d_in[2], (const int*)d_in[8]);
}